// round 11
// baseline (speedup 1.0000x reference)
#include <cuda_runtime.h>
#include <cuda_fp16.h>
#include <cstdint>

#define NDIM 16384
#define BDIM 512
#define NNZ  131072
#define B4   (BDIM/4)   // 128 float4 / uint2 per column
#define PGRID 1776      // 148 SMs x 12 resident CTAs (persistent k_iter grid)

// ---------------- device scratch (static allocation; no cudaMalloc) -------------
__device__ __align__(16) __half g_hh0[(size_t)NDIM * BDIM];   // h ping (N,B) fp16
__device__ __align__(16) __half g_hh1[(size_t)NDIM * BDIM];   // h pong (N,B) fp16
__device__ __align__(16) __half g_ch [(size_t)NDIM * BDIM];   // cell state fp16
__device__ __align__(16) float  g_hfinal[(size_t)NDIM * BDIM];// final h fp32 (N,B)

__device__ int                g_colcnt[NDIM];
__device__ int                g_colstart[NDIM + 1];
__device__ int                g_cur[NDIM];
__device__ unsigned long long g_pack[NNZ];      // [45:32]=row [31:0]=val bits
__device__ int                g_idx_nonzero_odd = 0;   // monotonic 0->1; pure fn of input

// ---------------- init: zero counters + index-dtype detection (fused) ------------
__global__ void k_init(const int* __restrict__ w) {
    int i = blockIdx.x * blockDim.x + threadIdx.x;
    if (i < NDIM) g_colcnt[i] = 0;
    if (i < NNZ && w[2 * i + 1] != 0) atomicOr(&g_idx_nonzero_odd, 1);
}

__device__ __forceinline__ void load_rc(const void* idx, int e, int& row, int& col) {
    if (g_idx_nonzero_odd) {               // int32 pairs
        const int* p = (const int*)idx;
        row = p[2 * e + 0];
        col = p[2 * e + 1];
    } else {                               // int64 pairs
        const long long* p = (const long long*)idx;
        row = (int)p[2 * e + 0];
        col = (int)p[2 * e + 1];
    }
    row &= (NDIM - 1);
    col &= (NDIM - 1);
}

__global__ void k_hist(const void* __restrict__ idx) {
    int e = blockIdx.x * blockDim.x + threadIdx.x;
    if (e < NNZ) {
        int row, col;
        load_rc(idx, e, row, col);
        atomicAdd(&g_colcnt[col], 1);
    }
}

// 1024 threads, 1 block: int4 loads, shfl warp scan + block scan over warp sums
__global__ void __launch_bounds__(1024) k_scan() {
    __shared__ int ws[32];
    int t = threadIdx.x;                 // 0..1023, owns 16 consecutive bins
    const int4* cc = (const int4*)g_colcnt;
    int4 a0 = cc[t * 4 + 0], a1 = cc[t * 4 + 1], a2 = cc[t * 4 + 2], a3 = cc[t * 4 + 3];
    int v[16] = {a0.x, a0.y, a0.z, a0.w, a1.x, a1.y, a1.z, a1.w,
                 a2.x, a2.y, a2.z, a2.w, a3.x, a3.y, a3.z, a3.w};
    int tot = 0;
    #pragma unroll
    for (int k = 0; k < 16; k++) tot += v[k];

    int lane = t & 31, w = t >> 5;
    int sc = tot;
    #pragma unroll
    for (int off = 1; off < 32; off <<= 1) {
        int n = __shfl_up_sync(0xffffffffu, sc, off);
        if (lane >= off) sc += n;
    }
    if (lane == 31) ws[w] = sc;
    __syncthreads();
    if (w == 0) {
        int x = ws[lane];
        #pragma unroll
        for (int off = 1; off < 32; off <<= 1) {
            int n = __shfl_up_sync(0xffffffffu, x, off);
            if (lane >= off) x += n;
        }
        ws[lane] = x;
    }
    __syncthreads();
    int base = (w ? ws[w - 1] : 0) + (sc - tot);
    #pragma unroll
    for (int k = 0; k < 16; k++) {
        g_colstart[t * 16 + k] = base;
        g_cur[t * 16 + k] = base;
        base += v[k];
    }
    if (t == 1023) g_colstart[NDIM] = base;   // == NNZ
}

__global__ void k_scatter(const void* __restrict__ idx,
                          const float* __restrict__ vals) {
    int e = blockIdx.x * blockDim.x + threadIdx.x;
    if (e < NNZ) {
        int row, col;
        load_rc(idx, e, row, col);
        int pos = atomicAdd(&g_cur[col], 1);
        unsigned long long p = ((unsigned long long)(unsigned)row << 32)
                             | (unsigned)__float_as_int(vals[e]);
        g_pack[pos] = p;
    }
}

// ---------------- transpose in: x (B,N) fp32 -> g_hh0 (N,B) fp16 -----------------
__global__ void k_transpose_in(const float* __restrict__ x) {
    __shared__ float tile[32][33];
    int nBase = blockIdx.x * 32;
    int bBase = blockIdx.y * 32;
    int tx = threadIdx.x, ty = threadIdx.y;
    #pragma unroll
    for (int i = ty; i < 32; i += 8)
        tile[i][tx] = x[(size_t)(bBase + i) * NDIM + nBase + tx];
    __syncthreads();
    #pragma unroll
    for (int i = ty; i < 32; i += 8)
        g_hh0[(size_t)(nBase + i) * BDIM + bBase + tx] = __float2half(tile[tx][i]);
}

// ---------------- fused SpMM + LSTM gate iteration ------------------------------
__device__ __forceinline__ float lstm_elem(float z, float& c,
                                           float ebi, float ebf, float ebo, float ebg2) {
    float ez = __expf(-z);
    float i = __fdividef(1.0f, 1.0f + ez * ebi);
    float f = __fdividef(1.0f, 1.0f + ez * ebf);
    float o = __fdividef(1.0f, 1.0f + ez * ebo);
    float w = ez * ez * ebg2;                         // e^{-2(z+b_g)}
    float g = __fdividef(2.0f, 1.0f + w) - 1.0f;      // tanh(z+b_g)
    c = f * c + i * g;
    float ec = __expf(-2.0f * c);
    float th = __fdividef(1.0f - ec, 1.0f + ec);      // tanh(c)
    return o * th;
}

__device__ __forceinline__ void gather_fma(const uint2* __restrict__ hp,
                                           unsigned long long p, int t, float4& acc) {
    int   r = (int)((p >> 32) & 0x3FFFu);
    float v = __int_as_float((int)(unsigned)p);
    uint2 hraw = hp[(size_t)r * B4 + t];
    float2 h01 = __half22float2(*(const __half2*)&hraw.x);
    float2 h23 = __half22float2(*(const __half2*)&hraw.y);
    acc.x = fmaf(v, h01.x, acc.x);
    acc.y = fmaf(v, h01.y, acc.y);
    acc.z = fmaf(v, h23.x, acc.z);
    acc.w = fmaf(v, h23.y, acc.w);
}

// Persistent: grid-stride over columns. One occupancy-wave per launch; no
// wave-transition cost (16384 tiny CTAs -> ~7 waves was ~8us/iter overhead).
// flip==0: read g_hh0 write g_hh1; flip==1: read g_hh1 write g_hh0.
// first: c starts at 0 (skip load). last: skip c store, write h fp32 into g_hfinal.
__global__ void __launch_bounds__(128)
k_iter(int flip, int first, int last,
       const float* __restrict__ bi_, const float* __restrict__ bf_,
       const float* __restrict__ bo_, const float* __restrict__ bg_) {
    const uint2* hp = (const uint2*)(flip ? g_hh1 : g_hh0);
    uint2*       hd = (uint2*)(flip ? g_hh0 : g_hh1);
    uint2*       chp = (uint2*)g_ch;
    int t = threadIdx.x;                   // 0..127, owns 4 batch elems

    for (int col = blockIdx.x; col < NDIM; col += PGRID) {
        int s = g_colstart[col], e = g_colstart[col + 1];

        // issue independent loads early: c state + bias exps overlap the gather
        size_t co = (size_t)col * B4 + t;
        uint2  craw = make_uint2(0u, 0u);
        if (!first) craw = chp[co];
        float ebi  = __expf(-bi_[col]);
        float ebf  = __expf(-bf_[col]);
        float ebo  = __expf(-bo_[col]);
        float ebg2 = __expf(-2.0f * bg_[col]);

        float4 acc = make_float4(0.f, 0.f, 0.f, 0.f);
        int j = s;
        // 4-deep pipelined main loop: 4 pack loads + 4 gathers before the FMAs
        for (; j + 4 <= e; j += 4) {
            unsigned long long p0 = g_pack[j + 0];
            unsigned long long p1 = g_pack[j + 1];
            unsigned long long p2 = g_pack[j + 2];
            unsigned long long p3 = g_pack[j + 3];
            int r0 = (int)((p0 >> 32) & 0x3FFFu);
            int r1 = (int)((p1 >> 32) & 0x3FFFu);
            int r2 = (int)((p2 >> 32) & 0x3FFFu);
            int r3 = (int)((p3 >> 32) & 0x3FFFu);
            uint2 h0 = hp[(size_t)r0 * B4 + t];
            uint2 h1 = hp[(size_t)r1 * B4 + t];
            uint2 h2 = hp[(size_t)r2 * B4 + t];
            uint2 h3 = hp[(size_t)r3 * B4 + t];
            float v0 = __int_as_float((int)(unsigned)p0);
            float v1 = __int_as_float((int)(unsigned)p1);
            float v2 = __int_as_float((int)(unsigned)p2);
            float v3 = __int_as_float((int)(unsigned)p3);
            float2 a01, a23;
            a01 = __half22float2(*(const __half2*)&h0.x); a23 = __half22float2(*(const __half2*)&h0.y);
            acc.x = fmaf(v0, a01.x, acc.x); acc.y = fmaf(v0, a01.y, acc.y);
            acc.z = fmaf(v0, a23.x, acc.z); acc.w = fmaf(v0, a23.y, acc.w);
            a01 = __half22float2(*(const __half2*)&h1.x); a23 = __half22float2(*(const __half2*)&h1.y);
            acc.x = fmaf(v1, a01.x, acc.x); acc.y = fmaf(v1, a01.y, acc.y);
            acc.z = fmaf(v1, a23.x, acc.z); acc.w = fmaf(v1, a23.y, acc.w);
            a01 = __half22float2(*(const __half2*)&h2.x); a23 = __half22float2(*(const __half2*)&h2.y);
            acc.x = fmaf(v2, a01.x, acc.x); acc.y = fmaf(v2, a01.y, acc.y);
            acc.z = fmaf(v2, a23.x, acc.z); acc.w = fmaf(v2, a23.y, acc.w);
            a01 = __half22float2(*(const __half2*)&h3.x); a23 = __half22float2(*(const __half2*)&h3.y);
            acc.x = fmaf(v3, a01.x, acc.x); acc.y = fmaf(v3, a01.y, acc.y);
            acc.z = fmaf(v3, a23.x, acc.z); acc.w = fmaf(v3, a23.y, acc.w);
        }
        for (; j < e; j++) gather_fma(hp, g_pack[j], t, acc);

        float2 c01 = __half22float2(*(const __half2*)&craw.x);
        float2 c23 = __half22float2(*(const __half2*)&craw.y);
        float4 cv = make_float4(c01.x, c01.y, c23.x, c23.y);

        float4 hout;
        hout.x = lstm_elem(acc.x, cv.x, ebi, ebf, ebo, ebg2);
        hout.y = lstm_elem(acc.y, cv.y, ebi, ebf, ebo, ebg2);
        hout.z = lstm_elem(acc.z, cv.z, ebi, ebf, ebo, ebg2);
        hout.w = lstm_elem(acc.w, cv.w, ebi, ebf, ebo, ebg2);

        if (last) {
            ((float4*)g_hfinal)[co] = hout;    // fp32-exact final h
        } else {
            uint2 cw;
            *(__half2*)&cw.x = __floats2half2_rn(cv.x, cv.y);
            *(__half2*)&cw.y = __floats2half2_rn(cv.z, cv.w);
            chp[co] = cw;
            uint2 hw;
            *(__half2*)&hw.x = __floats2half2_rn(hout.x, hout.y);
            *(__half2*)&hw.y = __floats2half2_rn(hout.z, hout.w);
            hd[co] = hw;
        }
    }
}

// ---------------- transpose out: g_hfinal (N,B) fp32 -> out (B,N) ----------------
__global__ void k_transpose_out(float* __restrict__ out) {
    __shared__ float tile[32][33];
    int nBase = blockIdx.x * 32;
    int bBase = blockIdx.y * 32;
    int tx = threadIdx.x, ty = threadIdx.y;
    #pragma unroll
    for (int i = ty; i < 32; i += 8)
        tile[i][tx] = g_hfinal[(size_t)(nBase + i) * BDIM + bBase + tx];
    __syncthreads();
    #pragma unroll
    for (int i = ty; i < 32; i += 8)
        out[(size_t)(bBase + i) * NDIM + nBase + tx] = tile[tx][i];
}

// ---------------- launch ---------------------------------------------------------
extern "C" void kernel_launch(void* const* d_in, const int* in_sizes, int n_in,
                              void* d_out, int out_size) {
    const float* x    = nullptr;
    const float* vals = nullptr;
    const float* bias[4] = {nullptr, nullptr, nullptr, nullptr};
    const void*  idx  = nullptr;
    int nbias = 0;
    for (int i = 0; i < n_in; i++) {
        int sz = in_sizes[i];
        if (sz == NDIM * BDIM)       x = (const float*)d_in[i];
        else if (sz == NNZ)          vals = (const float*)d_in[i];
        else if (sz == NDIM)         { if (nbias < 4) bias[nbias++] = (const float*)d_in[i]; }
        else                         idx = d_in[i];
    }
    const float* b_i = bias[0];
    const float* b_f = bias[1];
    const float* b_o = bias[2];
    const float* b_g = bias[3];
    float* out = (float*)d_out;
    (void)out_size;

    // build CSC
    k_init   <<<(NNZ + 255) / 256, 256>>>((const int*)idx);
    k_hist   <<<(NNZ + 255) / 256, 256>>>(idx);
    k_scan   <<<1, 1024>>>();
    k_scatter<<<(NNZ + 255) / 256, 256>>>(idx, vals);

    // state init: h = half(x^T); c handled by `first` flag
    dim3 tb(32, 8);
    dim3 tg(NDIM / 32, BDIM / 32);
    k_transpose_in<<<tg, tb>>>(x);

    // 4 fused iterations (persistent grids); last writes fp32 into g_hfinal
    k_iter<<<PGRID, 128>>>(0, 1, 0, b_i, b_f, b_o, b_g);
    k_iter<<<PGRID, 128>>>(1, 0, 0, b_i, b_f, b_o, b_g);
    k_iter<<<PGRID, 128>>>(0, 0, 0, b_i, b_f, b_o, b_g);
    k_iter<<<PGRID, 128>>>(1, 0, 1, b_i, b_f, b_o, b_g);

    // out (B,N) = transpose(g_hfinal)
    k_transpose_out<<<tg, tb>>>(out);
}

// round 12
// speedup vs baseline: 1.2856x; 1.2856x over previous
#include <cuda_runtime.h>
#include <cuda_fp16.h>
#include <cstdint>

#define NDIM 16384
#define BDIM 512
#define NNZ  131072
#define B8   (BDIM/8)   // 64 uint4 (8 halves) per column
#define B4f  (BDIM/4)   // 128 float4 per column (fp32 final h)

// ---------------- device scratch (static allocation; no cudaMalloc) -------------
__device__ __align__(16) __half g_hh0[(size_t)NDIM * BDIM];   // h ping (N,B) fp16
__device__ __align__(16) __half g_hh1[(size_t)NDIM * BDIM];   // h pong (N,B) fp16
__device__ __align__(16) __half g_ch [(size_t)NDIM * BDIM];   // cell state fp16
__device__ __align__(16) float  g_hfinal[(size_t)NDIM * BDIM];// final h fp32 (N,B)
__device__ __align__(16) float4 g_eb[NDIM];                   // {e^-bi, e^-bf, e^-bo, e^-2bg}

__device__ int                g_colcnt[NDIM];
__device__ int                g_colstart[NDIM + 1];
__device__ int                g_cur[NDIM];
__device__ unsigned long long g_pack[NNZ];      // [45:32]=row [31:0]=val bits
__device__ int                g_idx_nonzero_odd = 0;   // monotonic 0->1; pure fn of input

// ---------------- init: zero counters + sampled index-dtype detection ------------
// int64 data (values < 2^31) -> odd 32-bit words are zero hi-halves.
// int32 data -> odd words are column ids; 4096 random cols all-zero is impossible.
__global__ void k_init(const int* __restrict__ w) {
    int i = blockIdx.x * blockDim.x + threadIdx.x;
    if (i < NDIM) g_colcnt[i] = 0;
    if (i < 4096 && w[2 * i + 1] != 0) atomicOr(&g_idx_nonzero_odd, 1);
}

__device__ __forceinline__ void load_rc(const void* idx, int e, int& row, int& col) {
    if (g_idx_nonzero_odd) {               // int32 pairs
        const int* p = (const int*)idx;
        row = p[2 * e + 0];
        col = p[2 * e + 1];
    } else {                               // int64 pairs
        const long long* p = (const long long*)idx;
        row = (int)p[2 * e + 0];
        col = (int)p[2 * e + 1];
    }
    row &= (NDIM - 1);
    col &= (NDIM - 1);
}

__global__ void k_hist(const void* __restrict__ idx) {
    int e = blockIdx.x * blockDim.x + threadIdx.x;
    if (e < NNZ) {
        int row, col;
        load_rc(idx, e, row, col);
        atomicAdd(&g_colcnt[col], 1);
    }
}

// 1024 threads, 1 block: int4 loads, shfl warp scan + block scan over warp sums
__global__ void __launch_bounds__(1024) k_scan() {
    __shared__ int ws[32];
    int t = threadIdx.x;                 // 0..1023, owns 16 consecutive bins
    const int4* cc = (const int4*)g_colcnt;
    int4 a0 = cc[t * 4 + 0], a1 = cc[t * 4 + 1], a2 = cc[t * 4 + 2], a3 = cc[t * 4 + 3];
    int v[16] = {a0.x, a0.y, a0.z, a0.w, a1.x, a1.y, a1.z, a1.w,
                 a2.x, a2.y, a2.z, a2.w, a3.x, a3.y, a3.z, a3.w};
    int tot = 0;
    #pragma unroll
    for (int k = 0; k < 16; k++) tot += v[k];

    int lane = t & 31, w = t >> 5;
    int sc = tot;
    #pragma unroll
    for (int off = 1; off < 32; off <<= 1) {
        int n = __shfl_up_sync(0xffffffffu, sc, off);
        if (lane >= off) sc += n;
    }
    if (lane == 31) ws[w] = sc;
    __syncthreads();
    if (w == 0) {
        int x = ws[lane];
        #pragma unroll
        for (int off = 1; off < 32; off <<= 1) {
            int n = __shfl_up_sync(0xffffffffu, x, off);
            if (lane >= off) x += n;
        }
        ws[lane] = x;
    }
    __syncthreads();
    int base = (w ? ws[w - 1] : 0) + (sc - tot);
    #pragma unroll
    for (int k = 0; k < 16; k++) {
        g_colstart[t * 16 + k] = base;
        g_cur[t * 16 + k] = base;
        base += v[k];
    }
    if (t == 1023) g_colstart[NDIM] = base;   // == NNZ
}

__global__ void k_scatter(const void* __restrict__ idx,
                          const float* __restrict__ vals) {
    int e = blockIdx.x * blockDim.x + threadIdx.x;
    if (e < NNZ) {
        int row, col;
        load_rc(idx, e, row, col);
        int pos = atomicAdd(&g_cur[col], 1);
        unsigned long long p = ((unsigned long long)(unsigned)row << 32)
                             | (unsigned)__float_as_int(vals[e]);
        g_pack[pos] = p;
    }
}

// ---------------- precompute bias exponentials -----------------------------------
__global__ void k_ebias(const float* __restrict__ bi_, const float* __restrict__ bf_,
                        const float* __restrict__ bo_, const float* __restrict__ bg_) {
    int col = blockIdx.x * blockDim.x + threadIdx.x;
    if (col < NDIM) {
        g_eb[col] = make_float4(__expf(-bi_[col]), __expf(-bf_[col]),
                                __expf(-bo_[col]), __expf(-2.0f * bg_[col]));
    }
}

// ---------------- transpose in: x (B,N) fp32 -> g_hh0 (N,B) fp16 -----------------
__global__ void k_transpose_in(const float* __restrict__ x) {
    __shared__ float tile[32][33];
    int nBase = blockIdx.x * 32;
    int bBase = blockIdx.y * 32;
    int tx = threadIdx.x, ty = threadIdx.y;
    #pragma unroll
    for (int i = ty; i < 32; i += 8)
        tile[i][tx] = x[(size_t)(bBase + i) * NDIM + nBase + tx];
    __syncthreads();
    #pragma unroll
    for (int i = ty; i < 32; i += 8)
        g_hh0[(size_t)(nBase + i) * BDIM + bBase + tx] = __float2half(tile[tx][i]);
}

// ---------------- fused SpMM + LSTM gate iteration ------------------------------
__device__ __forceinline__ float lstm_elem(float z, float& c,
                                           float ebi, float ebf, float ebo, float ebg2) {
    float ez = __expf(-z);
    float i = __fdividef(1.0f, 1.0f + ez * ebi);
    float f = __fdividef(1.0f, 1.0f + ez * ebf);
    float o = __fdividef(1.0f, 1.0f + ez * ebo);
    float w = ez * ez * ebg2;                         // e^{-2(z+b_g)}
    float g = __fdividef(2.0f, 1.0f + w) - 1.0f;      // tanh(z+b_g)
    c = f * c + i * g;
    float ec = __expf(-2.0f * c);
    float th = __fdividef(1.0f - ec, 1.0f + ec);      // tanh(c)
    return o * th;
}

__device__ __forceinline__ void h8_fma(uint4 hr, float v, float* acc) {
    float2 a0 = __half22float2(*(const __half2*)&hr.x);
    float2 a1 = __half22float2(*(const __half2*)&hr.y);
    float2 a2 = __half22float2(*(const __half2*)&hr.z);
    float2 a3 = __half22float2(*(const __half2*)&hr.w);
    acc[0] = fmaf(v, a0.x, acc[0]); acc[1] = fmaf(v, a0.y, acc[1]);
    acc[2] = fmaf(v, a1.x, acc[2]); acc[3] = fmaf(v, a1.y, acc[3]);
    acc[4] = fmaf(v, a2.x, acc[4]); acc[5] = fmaf(v, a2.y, acc[5]);
    acc[6] = fmaf(v, a3.x, acc[6]); acc[7] = fmaf(v, a3.y, acc[7]);
}

// 64 threads/CTA, each thread owns 8 batch elems (one uint4 = 8 halves).
// flip==0: read g_hh0 write g_hh1; flip==1: read g_hh1 write g_hh0.
// first: c starts at 0 (skip load). last: skip c store, write h fp32 into g_hfinal.
__global__ void __launch_bounds__(64, 16)
k_iter(int flip, int first, int last) {
    const uint4* hp = (const uint4*)(flip ? g_hh1 : g_hh0);
    uint4*       hd = (uint4*)(flip ? g_hh0 : g_hh1);
    uint4*       chp = (uint4*)g_ch;

    int col = blockIdx.x;
    int t   = threadIdx.x;                 // 0..63
    int s = g_colstart[col], e = g_colstart[col + 1];

    // issue independent loads early: c state + bias-exp table
    size_t co = (size_t)col * B8 + t;
    uint4  craw = make_uint4(0u, 0u, 0u, 0u);
    if (!first) craw = chp[co];
    float4 eb = g_eb[col];

    float acc[8] = {0.f, 0.f, 0.f, 0.f, 0.f, 0.f, 0.f, 0.f};
    int j = s;
    // 4-deep pipelined main loop: 4 pack loads + 4 gathers before the FMAs
    for (; j + 4 <= e; j += 4) {
        unsigned long long p0 = g_pack[j + 0];
        unsigned long long p1 = g_pack[j + 1];
        unsigned long long p2 = g_pack[j + 2];
        unsigned long long p3 = g_pack[j + 3];
        int r0 = (int)((p0 >> 32) & 0x3FFFu);
        int r1 = (int)((p1 >> 32) & 0x3FFFu);
        int r2 = (int)((p2 >> 32) & 0x3FFFu);
        int r3 = (int)((p3 >> 32) & 0x3FFFu);
        uint4 h0 = hp[(size_t)r0 * B8 + t];
        uint4 h1 = hp[(size_t)r1 * B8 + t];
        uint4 h2 = hp[(size_t)r2 * B8 + t];
        uint4 h3 = hp[(size_t)r3 * B8 + t];
        h8_fma(h0, __int_as_float((int)(unsigned)p0), acc);
        h8_fma(h1, __int_as_float((int)(unsigned)p1), acc);
        h8_fma(h2, __int_as_float((int)(unsigned)p2), acc);
        h8_fma(h3, __int_as_float((int)(unsigned)p3), acc);
    }
    for (; j < e; j++) {
        unsigned long long p = g_pack[j];
        int r = (int)((p >> 32) & 0x3FFFu);
        uint4 hr = hp[(size_t)r * B8 + t];
        h8_fma(hr, __int_as_float((int)(unsigned)p), acc);
    }

    float cv[8];
    {
        float2 c0 = __half22float2(*(const __half2*)&craw.x);
        float2 c1 = __half22float2(*(const __half2*)&craw.y);
        float2 c2 = __half22float2(*(const __half2*)&craw.z);
        float2 c3 = __half22float2(*(const __half2*)&craw.w);
        cv[0] = c0.x; cv[1] = c0.y; cv[2] = c1.x; cv[3] = c1.y;
        cv[4] = c2.x; cv[5] = c2.y; cv[6] = c3.x; cv[7] = c3.y;
    }

    float hout[8];
    #pragma unroll
    for (int k = 0; k < 8; k++)
        hout[k] = lstm_elem(acc[k], cv[k], eb.x, eb.y, eb.z, eb.w);

    if (last) {
        float4* hf = (float4*)g_hfinal;
        size_t fo = (size_t)col * B4f + 2 * t;
        hf[fo + 0] = make_float4(hout[0], hout[1], hout[2], hout[3]);
        hf[fo + 1] = make_float4(hout[4], hout[5], hout[6], hout[7]);
    } else {
        uint4 cw;
        *(__half2*)&cw.x = __floats2half2_rn(cv[0], cv[1]);
        *(__half2*)&cw.y = __floats2half2_rn(cv[2], cv[3]);
        *(__half2*)&cw.z = __floats2half2_rn(cv[4], cv[5]);
        *(__half2*)&cw.w = __floats2half2_rn(cv[6], cv[7]);
        chp[co] = cw;
        uint4 hw;
        *(__half2*)&hw.x = __floats2half2_rn(hout[0], hout[1]);
        *(__half2*)&hw.y = __floats2half2_rn(hout[2], hout[3]);
        *(__half2*)&hw.z = __floats2half2_rn(hout[4], hout[5]);
        *(__half2*)&hw.w = __floats2half2_rn(hout[6], hout[7]);
        hd[co] = hw;
    }
}

// ---------------- transpose out: g_hfinal (N,B) fp32 -> out (B,N) ----------------
__global__ void k_transpose_out(float* __restrict__ out) {
    __shared__ float tile[32][33];
    int nBase = blockIdx.x * 32;
    int bBase = blockIdx.y * 32;
    int tx = threadIdx.x, ty = threadIdx.y;
    #pragma unroll
    for (int i = ty; i < 32; i += 8)
        tile[i][tx] = g_hfinal[(size_t)(nBase + i) * BDIM + bBase + tx];
    __syncthreads();
    #pragma unroll
    for (int i = ty; i < 32; i += 8)
        out[(size_t)(bBase + i) * NDIM + nBase + tx] = tile[tx][i];
}

// ---------------- launch ---------------------------------------------------------
extern "C" void kernel_launch(void* const* d_in, const int* in_sizes, int n_in,
                              void* d_out, int out_size) {
    const float* x    = nullptr;
    const float* vals = nullptr;
    const float* bias[4] = {nullptr, nullptr, nullptr, nullptr};
    const void*  idx  = nullptr;
    int nbias = 0;
    for (int i = 0; i < n_in; i++) {
        int sz = in_sizes[i];
        if (sz == NDIM * BDIM)       x = (const float*)d_in[i];
        else if (sz == NNZ)          vals = (const float*)d_in[i];
        else if (sz == NDIM)         { if (nbias < 4) bias[nbias++] = (const float*)d_in[i]; }
        else                         idx = d_in[i];
    }
    float* out = (float*)d_out;
    (void)out_size;

    // build CSC + bias-exp table
    k_init   <<<(NDIM + 255) / 256, 256>>>((const int*)idx);
    k_hist   <<<(NNZ + 255) / 256, 256>>>(idx);
    k_scan   <<<1, 1024>>>();
    k_scatter<<<(NNZ + 255) / 256, 256>>>(idx, vals);
    k_ebias  <<<(NDIM + 255) / 256, 256>>>(bias[0], bias[1], bias[2], bias[3]);

    // state init: h = half(x^T); c handled by `first` flag
    dim3 tb(32, 8);
    dim3 tg(NDIM / 32, BDIM / 32);
    k_transpose_in<<<tg, tb>>>(x);

    // 4 fused iterations; h ping-pong; last writes fp32 into g_hfinal
    k_iter<<<NDIM, 64>>>(0, 1, 0);
    k_iter<<<NDIM, 64>>>(1, 0, 0);
    k_iter<<<NDIM, 64>>>(0, 0, 0);
    k_iter<<<NDIM, 64>>>(1, 0, 1);

    // out (B,N) = transpose(g_hfinal)
    k_transpose_out<<<tg, tb>>>(out);
}